// round 9
// baseline (speedup 1.0000x reference)
#include <cuda_runtime.h>

// Problem shape (dataset-fixed): B=32, N=64, L=128, D=256, NB=2048, MAX_LEN=8192.
// Sizes derived at launch; static scratch sized with headroom.

#define T_CHUNK 128          // t-positions per block

// Static device scratch (allocation-free rule). g_cnt is zero-initialized and
// reset by the last block of each batch row (graph-replay safe).
__device__ float g_partial[1048576];   // B * nchunks * D partials
__device__ int   g_cnt[128];           // per-batch arrival counters

// ---------------------------------------------------------------------------
// Single fused kernel: grid = (MAX_LEN/T_CHUNK, B), block = 256.
//   d4 = tid & 63 : float4 lane over D=256
//   ts = tid >> 6 : one of 4 t-subgroups
__global__ void __launch_bounds__(256)
k_all(const float4* __restrict__ mb,
      float4* __restrict__ mb_out,
      const float* __restrict__ src,
      const int* __restrict__ recover,
      float* __restrict__ src_out,
      float* __restrict__ hid_out,
      float* __restrict__ len_out,
      const int* __restrict__ lengths,
      int B, int N, int NB, int Dv, int nchunks)
{
    __shared__ int    soff[1056];       // N+1 exclusive offsets (+ total at [N])
    __shared__ int    stok[T_CHUNK];    // token index per t in chunk (-1 = pad)
    __shared__ float4 sred[256];
    __shared__ int    s_last;

    int b     = blockIdx.y;
    int chunk = blockIdx.x;
    int t0    = chunk * T_CHUNK;
    int tid   = threadIdx.x;
    int nbase = b * N;

    // ---- Phase 0: in-block offset scan (warp 0, shuffle) ----
    if (N == 64) {
        if (tid < 32) {
            int l0 = __ldg(&lengths[nbase + 2 * tid]);
            int l1 = __ldg(&lengths[nbase + 2 * tid + 1]);
            int s  = l0 + l1;
            #pragma unroll
            for (int st = 1; st < 32; st <<= 1) {
                int v = __shfl_up_sync(0xffffffffu, s, st);
                if (tid >= st) s += v;
            }
            soff[2 * tid + 1] = s - l1;
            soff[2 * tid + 2] = s;
            if (tid == 0) soff[0] = 0;
        }
    } else {
        if (tid == 0) {
            int acc = 0;
            soff[0] = 0;
            for (int n = 0; n < N; n++) { acc += lengths[nbase + n]; soff[n + 1] = acc; }
        }
    }
    __syncthreads();
    int total = soff[N];
    if (chunk == 0 && tid == 0)
        len_out[b] = (float)total;

    // ---- Phase 1: resolve each t -> token via independent binary search ----
    if (tid < T_CHUNK) {
        int t = t0 + tid;
        int tok = -1;
        float sval = 1.0f;
        if (t < total) {
            int lo = 0, hi = N - 1;                // largest n: soff[n] <= t
            while (lo < hi) {
                int mid = (lo + hi + 1) >> 1;
                if (soff[mid] <= t) lo = mid; else hi = mid - 1;
            }
            int p = t - soff[lo];
            tok  = p * NB + nbase + lo;
            sval = src[p * NB + __ldg(&recover[nbase + lo])];
        }
        stok[tid] = tok;
        src_out[t * B + b] = sval;
    }
    __syncthreads();

    // ---- Phase 2: main stream with 4-deep independent load batching ----
    int d4 = tid & 63;
    int ts = tid >> 6;

    float4 acc = make_float4(0.f, 0.f, 0.f, 0.f);
    const float4 zero = make_float4(0.f, 0.f, 0.f, 0.f);

    long wbase = (long)(t0 * B + b) * Dv + d4;     // mb_out index for tt=0
    long wstr  = (long)B * Dv;                     // per-t stride

    #pragma unroll
    for (int step = 0; step < T_CHUNK / 16; step++) {
        int base = step * 16 + ts;                 // rows: base, +4, +8, +12
        int tok0 = stok[base];
        int tok1 = stok[base + 4];
        int tok2 = stok[base + 8];
        int tok3 = stok[base + 12];

        float4 v0 = zero, v1 = zero, v2 = zero, v3 = zero;
        if (tok0 >= 0) v0 = __ldcs(&mb[(long)tok0 * Dv + d4]);
        if (tok1 >= 0) v1 = __ldcs(&mb[(long)tok1 * Dv + d4]);
        if (tok2 >= 0) v2 = __ldcs(&mb[(long)tok2 * Dv + d4]);
        if (tok3 >= 0) v3 = __ldcs(&mb[(long)tok3 * Dv + d4]);

        __stcs(&mb_out[wbase + (long)(base)      * wstr], v0);
        __stcs(&mb_out[wbase + (long)(base + 4)  * wstr], v1);
        __stcs(&mb_out[wbase + (long)(base + 8)  * wstr], v2);
        __stcs(&mb_out[wbase + (long)(base + 12) * wstr], v3);

        acc.x += (v0.x + v1.x) + (v2.x + v3.x);
        acc.y += (v0.y + v1.y) + (v2.y + v3.y);
        acc.z += (v0.z + v1.z) + (v2.z + v3.z);
        acc.w += (v0.w + v1.w) + (v2.w + v3.w);
    }

    // ---- Phase 3: deterministic block reduction -> chunk partial ----
    sred[tid] = acc;
    __syncthreads();
    if (ts == 0) {
        float4 a0 = sred[d4];
        float4 a1 = sred[64  + d4];
        float4 a2 = sred[128 + d4];
        float4 a3 = sred[192 + d4];
        float4 tot;
        tot.x = (a0.x + a1.x) + (a2.x + a3.x);
        tot.y = (a0.y + a1.y) + (a2.y + a3.y);
        tot.z = (a0.z + a1.z) + (a2.z + a3.z);
        tot.w = (a0.w + a1.w) + (a2.w + a3.w);
        float4* pp = (float4*)g_partial;
        pp[(long)(b * nchunks + chunk) * Dv + d4] = tot;
    }

    // ---- Phase 4: publish via single acq_rel atomic; last block reduces ----
    __syncthreads();                               // partial stores done block-wide
    if (tid == 0) {
        int old;
        asm volatile("atom.add.acq_rel.gpu.global.s32 %0, [%1], 1;"
                     : "=r"(old) : "l"(&g_cnt[b]) : "memory");
        s_last = (old == nchunks - 1);
    }
    __syncthreads();
    if (s_last) {
        // low-register tail: 4 accumulators, unroll 4, fixed order (determinism)
        int D = Dv * 4;
        float inv = 1.0f / (float)total;
        for (int d = tid; d < D; d += blockDim.x) {
            const float* p = g_partial + (long)b * nchunks * D + d;
            float s0 = 0.f, s1 = 0.f, s2 = 0.f, s3 = 0.f;
            #pragma unroll 1
            for (int c = 0; c < nchunks; c += 4) {
                s0 += p[(long)(c + 0) * D];
                s1 += p[(long)(c + 1) * D];
                s2 += p[(long)(c + 2) * D];
                s3 += p[(long)(c + 3) * D];
            }
            hid_out[b * D + d] = ((s0 + s1) + (s2 + s3)) * inv;
        }
        if (tid == 0) g_cnt[b] = 0;                // reset for graph replay
    }
}

// ---------------------------------------------------------------------------
extern "C" void kernel_launch(void* const* d_in, const int* in_sizes, int n_in,
                              void* d_out, int out_size)
{
    const float* src     = (const float*)d_in[0];   // [L, NB, 1]
    const float* mb      = (const float*)d_in[1];   // [L, NB, D]
    const int*   lengths = (const int*)  d_in[2];   // [NB]
    const int*   recover = (const int*)  d_in[3];   // [NB]

    int NB = in_sizes[2];
    int L  = in_sizes[0] / NB;
    int D  = in_sizes[1] / in_sizes[0];

    // out_size = NB*L*(1+D) + B*(D+1)  ->  solve for B.
    long rem = (long)out_size - (long)NB * L * (1 + D);
    int B = (int)(rem / (D + 1));
    int N = NB / B;
    int MAX_LEN = N * L;

    float* out      = (float*)d_out;
    float* src_out  = out;                                   // [MAX_LEN, B, 1]
    float* mb_out   = out + (long)MAX_LEN * B;               // [MAX_LEN, B, D]
    float* hid_out  = mb_out + (long)MAX_LEN * B * D;        // [1, B, D]
    float* len_out  = hid_out + (long)B * D;                 // [B]

    int nchunks = MAX_LEN / T_CHUNK;                         // 64
    dim3 grid(nchunks, B);                                   // 2048 blocks
    k_all<<<grid, 256>>>((const float4*)mb, (float4*)mb_out,
                         src, recover, src_out, hid_out, len_out,
                         lengths, B, N, NB, D / 4, nchunks);
}

// round 10
// speedup vs baseline: 1.0359x; 1.0359x over previous
#include <cuda_runtime.h>

// Problem shape (dataset-fixed): B=32, N=64, L=128, D=256, NB=2048, MAX_LEN=8192.
// Sizes derived at launch; static scratch sized with headroom.

#define T_CHUNK 128          // t-positions per block (blockDim = 128)

// Static device scratch (allocation-free rule).
__device__ float g_partial[1048576];   // B * nchunks * D partials
__device__ float g_lenf[128];          // per-batch total length

// ---------------------------------------------------------------------------
// Main kernel: grid = (MAX_LEN/T_CHUNK, B), block = 128.
//   d4 = tid & 63 : float4 lane over D=256
//   ts = tid >> 6 : one of 2 t-subgroups
// 128-thread CTAs -> 16 CTAs/SM -> whole 2048-block grid resident in ONE wave.
__global__ void __launch_bounds__(128)
k_main(const float4* __restrict__ mb,
       float4* __restrict__ mb_out,
       const float* __restrict__ src,
       const int* __restrict__ recover,
       float* __restrict__ src_out,
       float* __restrict__ len_out,
       const int* __restrict__ lengths,
       int B, int N, int NB, int Dv, int nchunks)
{
    __shared__ int    soff[1056];       // N+1 exclusive offsets (+ total at [N])
    __shared__ int    stok[T_CHUNK];    // token index per t in chunk (-1 = pad)
    __shared__ float4 sred[128];

    int b     = blockIdx.y;
    int chunk = blockIdx.x;
    int t0    = chunk * T_CHUNK;
    int tid   = threadIdx.x;
    int nbase = b * N;

    // ---- Phase 0: in-block offset scan (warp 0, shuffle) ----
    if (N == 64) {
        if (tid < 32) {
            int l0 = __ldg(&lengths[nbase + 2 * tid]);
            int l1 = __ldg(&lengths[nbase + 2 * tid + 1]);
            int s  = l0 + l1;
            #pragma unroll
            for (int st = 1; st < 32; st <<= 1) {
                int v = __shfl_up_sync(0xffffffffu, s, st);
                if (tid >= st) s += v;
            }
            soff[2 * tid + 1] = s - l1;
            soff[2 * tid + 2] = s;
            if (tid == 0) soff[0] = 0;
        }
    } else {
        if (tid == 0) {
            int acc = 0;
            soff[0] = 0;
            for (int n = 0; n < N; n++) { acc += lengths[nbase + n]; soff[n + 1] = acc; }
        }
    }
    __syncthreads();
    int total = soff[N];
    if (chunk == 0 && tid == 0) {
        len_out[b] = (float)total;
        g_lenf[b]  = (float)total;
    }

    // ---- Phase 1: resolve each t -> token via independent binary search ----
    {
        int t = t0 + tid;                          // blockDim == T_CHUNK
        int tok = -1;
        float sval = 1.0f;
        if (t < total) {
            int lo = 0, hi = N - 1;                // largest n: soff[n] <= t
            while (lo < hi) {
                int mid = (lo + hi + 1) >> 1;
                if (soff[mid] <= t) lo = mid; else hi = mid - 1;
            }
            int p = t - soff[lo];
            tok  = p * NB + nbase + lo;
            sval = src[p * NB + __ldg(&recover[nbase + lo])];
        }
        stok[tid] = tok;
        src_out[t * B + b] = sval;
    }
    __syncthreads();

    // ---- Phase 2: main stream, 2 t-subgroups, 4-deep load batching ----
    int d4 = tid & 63;
    int ts = tid >> 6;

    float4 acc = make_float4(0.f, 0.f, 0.f, 0.f);
    const float4 zero = make_float4(0.f, 0.f, 0.f, 0.f);

    long wbase = (long)(t0 * B + b) * Dv + d4;     // mb_out index for tt=0
    long wstr  = (long)B * Dv;                     // per-t stride

    #pragma unroll
    for (int step = 0; step < T_CHUNK / 8; step++) {
        int base = step * 8 + ts;                  // rows: base, +2, +4, +6
        int tok0 = stok[base];
        int tok1 = stok[base + 2];
        int tok2 = stok[base + 4];
        int tok3 = stok[base + 6];

        float4 v0 = zero, v1 = zero, v2 = zero, v3 = zero;
        if (tok0 >= 0) v0 = __ldcs(&mb[(long)tok0 * Dv + d4]);
        if (tok1 >= 0) v1 = __ldcs(&mb[(long)tok1 * Dv + d4]);
        if (tok2 >= 0) v2 = __ldcs(&mb[(long)tok2 * Dv + d4]);
        if (tok3 >= 0) v3 = __ldcs(&mb[(long)tok3 * Dv + d4]);

        __stcs(&mb_out[wbase + (long)(base)     * wstr], v0);
        __stcs(&mb_out[wbase + (long)(base + 2) * wstr], v1);
        __stcs(&mb_out[wbase + (long)(base + 4) * wstr], v2);
        __stcs(&mb_out[wbase + (long)(base + 6) * wstr], v3);

        acc.x += (v0.x + v1.x) + (v2.x + v3.x);
        acc.y += (v0.y + v1.y) + (v2.y + v3.y);
        acc.z += (v0.z + v1.z) + (v2.z + v3.z);
        acc.w += (v0.w + v1.w) + (v2.w + v3.w);
    }

    // ---- Phase 3: deterministic block reduction -> chunk partial ----
    sred[tid] = acc;
    __syncthreads();
    if (ts == 0) {
        float4 a0 = sred[d4];
        float4 a1 = sred[64 + d4];
        float4 tot;
        tot.x = a0.x + a1.x;
        tot.y = a0.y + a1.y;
        tot.z = a0.z + a1.z;
        tot.w = a0.w + a1.w;
        float4* pp = (float4*)g_partial;
        pp[(long)(b * nchunks + chunk) * Dv + d4] = tot;
    }
}

// ---------------------------------------------------------------------------
// Final: grid = (B, D/64), block = 256.
//   dl = tid & 63 (d within slice), cg = tid >> 6 (4 chunk groups of nch/4).
__global__ void __launch_bounds__(256)
k_final(float* __restrict__ hid_out, int D, int nch)
{
    __shared__ float sred[256];
    int b   = blockIdx.x;
    int d0  = blockIdx.y * 64;
    int tid = threadIdx.x;
    int dl  = tid & 63;
    int cg  = tid >> 6;                 // 0..3
    int cpg = nch / 4;                  // 16

    const float* p = g_partial + ((long)b * nch + (long)cg * cpg) * D + d0 + dl;
    float s = 0.f;
    #pragma unroll 16
    for (int c = 0; c < cpg; c++)
        s += p[(long)c * D];

    sred[tid] = s;
    __syncthreads();
    if (cg == 0) {
        float tot = (sred[dl] + sred[64 + dl]) + (sred[128 + dl] + sred[192 + dl]);
        hid_out[b * D + d0 + dl] = tot / g_lenf[b];
    }
}

// ---------------------------------------------------------------------------
extern "C" void kernel_launch(void* const* d_in, const int* in_sizes, int n_in,
                              void* d_out, int out_size)
{
    const float* src     = (const float*)d_in[0];   // [L, NB, 1]
    const float* mb      = (const float*)d_in[1];   // [L, NB, D]
    const int*   lengths = (const int*)  d_in[2];   // [NB]
    const int*   recover = (const int*)  d_in[3];   // [NB]

    int NB = in_sizes[2];
    int L  = in_sizes[0] / NB;
    int D  = in_sizes[1] / in_sizes[0];

    // out_size = NB*L*(1+D) + B*(D+1)  ->  solve for B.
    long rem = (long)out_size - (long)NB * L * (1 + D);
    int B = (int)(rem / (D + 1));
    int N = NB / B;
    int MAX_LEN = N * L;

    float* out      = (float*)d_out;
    float* src_out  = out;                                   // [MAX_LEN, B, 1]
    float* mb_out   = out + (long)MAX_LEN * B;               // [MAX_LEN, B, D]
    float* hid_out  = mb_out + (long)MAX_LEN * B * D;        // [1, B, D]
    float* len_out  = hid_out + (long)B * D;                 // [B]

    int nchunks = MAX_LEN / T_CHUNK;                         // 64
    dim3 grid(nchunks, B);                                   // 2048 blocks
    k_main<<<grid, 128>>>((const float4*)mb, (float4*)mb_out,
                          src, recover, src_out, len_out,
                          lengths, B, N, NB, D / 4, nchunks);

    dim3 gridF(B, D / 64);                                   // 128 blocks
    k_final<<<gridF, 256>>>(hid_out, D, nchunks);
}

// round 11
// speedup vs baseline: 1.0582x; 1.0216x over previous
#include <cuda_runtime.h>

// Problem shape (dataset-fixed): B=32, N=64, L=128, D=256, NB=2048, MAX_LEN=8192.
// Sizes derived at launch; static scratch sized with headroom.

#define T_CHUNK 128          // t-positions per block

// Static device scratch (allocation-free rule).
__device__ float g_partial[1048576];   // B * nchunks * D partials
__device__ float g_lenf[128];          // per-batch total length

// ---------------------------------------------------------------------------
// Main kernel: grid = (MAX_LEN/T_CHUNK, B), block = 256.  (R7 configuration)
//   d4 = tid & 63 : float4 lane over D=256
//   ts = tid >> 6 : one of 4 t-subgroups
__global__ void __launch_bounds__(256)
k_main(const float4* __restrict__ mb,
       float4* __restrict__ mb_out,
       const float* __restrict__ src,
       const int* __restrict__ recover,
       float* __restrict__ src_out,
       float* __restrict__ len_out,
       const int* __restrict__ lengths,
       int B, int N, int NB, int Dv, int nchunks)
{
    __shared__ int    soff[1056];       // N+1 exclusive offsets (+ total at [N])
    __shared__ int    stok[T_CHUNK];    // token index per t in chunk (-1 = pad)
    __shared__ float4 sred[256];

    int b     = blockIdx.y;
    int chunk = blockIdx.x;
    int t0    = chunk * T_CHUNK;
    int tid   = threadIdx.x;
    int nbase = b * N;

    // ---- Phase 0: in-block offset scan (warp 0, shuffle) ----
    if (N == 64) {
        if (tid < 32) {
            int l0 = __ldg(&lengths[nbase + 2 * tid]);
            int l1 = __ldg(&lengths[nbase + 2 * tid + 1]);
            int s  = l0 + l1;
            #pragma unroll
            for (int st = 1; st < 32; st <<= 1) {
                int v = __shfl_up_sync(0xffffffffu, s, st);
                if (tid >= st) s += v;
            }
            soff[2 * tid + 1] = s - l1;
            soff[2 * tid + 2] = s;
            if (tid == 0) soff[0] = 0;
        }
    } else {
        if (tid == 0) {
            int acc = 0;
            soff[0] = 0;
            for (int n = 0; n < N; n++) { acc += lengths[nbase + n]; soff[n + 1] = acc; }
        }
    }
    __syncthreads();
    int total = soff[N];
    if (chunk == 0 && tid == 0) {
        len_out[b] = (float)total;
        g_lenf[b]  = (float)total;
    }

    // ---- Phase 1: resolve each t -> token via independent binary search ----
    if (tid < T_CHUNK) {
        int t = t0 + tid;
        int tok = -1;
        float sval = 1.0f;
        if (t < total) {
            int lo = 0, hi = N - 1;                // largest n: soff[n] <= t
            while (lo < hi) {
                int mid = (lo + hi + 1) >> 1;
                if (soff[mid] <= t) lo = mid; else hi = mid - 1;
            }
            int p = t - soff[lo];
            tok  = p * NB + nbase + lo;
            sval = src[p * NB + __ldg(&recover[nbase + lo])];
        }
        stok[tid] = tok;
        src_out[t * B + b] = sval;
    }
    __syncthreads();

    // ---- Phase 2: main stream with explicit 8-deep load batching ----
    int d4 = tid & 63;
    int ts = tid >> 6;

    float4 acc = make_float4(0.f, 0.f, 0.f, 0.f);
    const float4 zero = make_float4(0.f, 0.f, 0.f, 0.f);

    long wbase = (long)(t0 * B + b) * Dv + d4;     // mb_out index for tt=0
    long wstr  = (long)B * Dv;                     // per-t stride

    #pragma unroll
    for (int step = 0; step < T_CHUNK / 32; step++) {
        int base = step * 32 + ts;                 // rows: base, +4, ..., +28
        int tok0 = stok[base];
        int tok1 = stok[base + 4];
        int tok2 = stok[base + 8];
        int tok3 = stok[base + 12];
        int tok4 = stok[base + 16];
        int tok5 = stok[base + 20];
        int tok6 = stok[base + 24];
        int tok7 = stok[base + 28];

        float4 v0 = zero, v1 = zero, v2 = zero, v3 = zero;
        float4 v4 = zero, v5 = zero, v6 = zero, v7 = zero;
        if (tok0 >= 0) v0 = __ldcs(&mb[(long)tok0 * Dv + d4]);
        if (tok1 >= 0) v1 = __ldcs(&mb[(long)tok1 * Dv + d4]);
        if (tok2 >= 0) v2 = __ldcs(&mb[(long)tok2 * Dv + d4]);
        if (tok3 >= 0) v3 = __ldcs(&mb[(long)tok3 * Dv + d4]);
        if (tok4 >= 0) v4 = __ldcs(&mb[(long)tok4 * Dv + d4]);
        if (tok5 >= 0) v5 = __ldcs(&mb[(long)tok5 * Dv + d4]);
        if (tok6 >= 0) v6 = __ldcs(&mb[(long)tok6 * Dv + d4]);
        if (tok7 >= 0) v7 = __ldcs(&mb[(long)tok7 * Dv + d4]);

        __stcs(&mb_out[wbase + (long)(base)      * wstr], v0);
        __stcs(&mb_out[wbase + (long)(base + 4)  * wstr], v1);
        __stcs(&mb_out[wbase + (long)(base + 8)  * wstr], v2);
        __stcs(&mb_out[wbase + (long)(base + 12) * wstr], v3);
        __stcs(&mb_out[wbase + (long)(base + 16) * wstr], v4);
        __stcs(&mb_out[wbase + (long)(base + 20) * wstr], v5);
        __stcs(&mb_out[wbase + (long)(base + 24) * wstr], v6);
        __stcs(&mb_out[wbase + (long)(base + 28) * wstr], v7);

        acc.x += ((v0.x + v1.x) + (v2.x + v3.x)) + ((v4.x + v5.x) + (v6.x + v7.x));
        acc.y += ((v0.y + v1.y) + (v2.y + v3.y)) + ((v4.y + v5.y) + (v6.y + v7.y));
        acc.z += ((v0.z + v1.z) + (v2.z + v3.z)) + ((v4.z + v5.z) + (v6.z + v7.z));
        acc.w += ((v0.w + v1.w) + (v2.w + v3.w)) + ((v4.w + v5.w) + (v6.w + v7.w));
    }

    // ---- Phase 3: deterministic block reduction -> chunk partial ----
    sred[tid] = acc;
    __syncthreads();
    if (ts == 0) {
        float4 a0 = sred[d4];
        float4 a1 = sred[64  + d4];
        float4 a2 = sred[128 + d4];
        float4 a3 = sred[192 + d4];
        float4 tot;
        tot.x = (a0.x + a1.x) + (a2.x + a3.x);
        tot.y = (a0.y + a1.y) + (a2.y + a3.y);
        tot.z = (a0.z + a1.z) + (a2.z + a3.z);
        tot.w = (a0.w + a1.w) + (a2.w + a3.w);
        float4* pp = (float4*)g_partial;
        pp[(long)(b * nchunks + chunk) * Dv + d4] = tot;
    }

    // PDL: allow the dependent kernel (k_final) to begin launching/prologue.
    // Memory visibility for g_partial is enforced by griddepcontrol.wait in
    // k_final (which waits for this grid's memory ops), so this is safe.
    asm volatile("griddepcontrol.launch_dependents;" ::: "memory");
}

// ---------------------------------------------------------------------------
// Final: grid = (B, D/64), block = 256.  Launched with programmatic stream
// serialization: blocks spin up during k_main's tail; the wait below blocks
// until ALL of k_main's global writes (g_partial, g_lenf) are visible.
__global__ void __launch_bounds__(256)
k_final(float* __restrict__ hid_out, int D, int nch)
{
    asm volatile("griddepcontrol.wait;" ::: "memory");

    __shared__ float sred[256];
    int b   = blockIdx.x;
    int d0  = blockIdx.y * 64;
    int tid = threadIdx.x;
    int dl  = tid & 63;
    int cg  = tid >> 6;                 // 0..3
    int cpg = nch / 4;                  // 16

    const float* p = g_partial + ((long)b * nch + (long)cg * cpg) * D + d0 + dl;
    float s = 0.f;
    #pragma unroll 16
    for (int c = 0; c < cpg; c++)
        s += p[(long)c * D];

    sred[tid] = s;
    __syncthreads();
    if (cg == 0) {
        float tot = (sred[dl] + sred[64 + dl]) + (sred[128 + dl] + sred[192 + dl]);
        hid_out[b * D + d0 + dl] = tot / g_lenf[b];
    }
}

// ---------------------------------------------------------------------------
extern "C" void kernel_launch(void* const* d_in, const int* in_sizes, int n_in,
                              void* d_out, int out_size)
{
    const float* src     = (const float*)d_in[0];   // [L, NB, 1]
    const float* mb      = (const float*)d_in[1];   // [L, NB, D]
    const int*   lengths = (const int*)  d_in[2];   // [NB]
    const int*   recover = (const int*)  d_in[3];   // [NB]

    int NB = in_sizes[2];
    int L  = in_sizes[0] / NB;
    int D  = in_sizes[1] / in_sizes[0];

    // out_size = NB*L*(1+D) + B*(D+1)  ->  solve for B.
    long rem = (long)out_size - (long)NB * L * (1 + D);
    int B = (int)(rem / (D + 1));
    int N = NB / B;
    int MAX_LEN = N * L;

    float* out      = (float*)d_out;
    float* src_out  = out;                                   // [MAX_LEN, B, 1]
    float* mb_out   = out + (long)MAX_LEN * B;               // [MAX_LEN, B, D]
    float* hid_out  = mb_out + (long)MAX_LEN * B * D;        // [1, B, D]
    float* len_out  = hid_out + (long)B * D;                 // [B]

    int nchunks = MAX_LEN / T_CHUNK;                         // 64
    dim3 grid(nchunks, B);                                   // 2048 blocks
    k_main<<<grid, 256>>>((const float4*)mb, (float4*)mb_out,
                          src, recover, src_out, len_out,
                          lengths, B, N, NB, D / 4, nchunks);

    // k_final with programmatic dependent launch (overlap launch with k_main tail)
    cudaLaunchConfig_t cfg = {};
    cfg.gridDim  = dim3(B, D / 64);
    cfg.blockDim = dim3(256);
    cudaLaunchAttribute attr[1];
    attr[0].id = cudaLaunchAttributeProgrammaticStreamSerialization;
    attr[0].val.programmaticStreamSerializationAllowed = 1;
    cfg.attrs    = attr;
    cfg.numAttrs = 1;
    cudaLaunchKernelEx(&cfg, k_final, hid_out, D, nchunks);
}

// round 12
// speedup vs baseline: 1.1277x; 1.0657x over previous
#include <cuda_runtime.h>

// Problem shape (dataset-fixed): B=32, N=64, L=128, D=256, NB=2048, MAX_LEN=8192.
// Sizes derived at launch; static scratch sized with headroom.

#define T_CHUNK 128          // t-positions per block

// Static device scratch (allocation-free rule).
__device__ float g_partial[1048576];   // B * nchunks * D partials
__device__ float g_lenf[128];          // per-batch total length

// ---------------------------------------------------------------------------
// Main kernel: grid = (B, MAX_LEN/T_CHUNK), block = 256.
// b = blockIdx.x (FASTEST-varying) so co-resident CTAs cover all b for a few
// consecutive chunks -> mb_out writes tile dense contiguous DRAM spans.
//   d4 = tid & 63 : float4 lane over D=256
//   ts = tid >> 6 : one of 4 t-subgroups
__global__ void __launch_bounds__(256)
k_main(const float4* __restrict__ mb,
       float4* __restrict__ mb_out,
       const float* __restrict__ src,
       const int* __restrict__ recover,
       float* __restrict__ src_out,
       float* __restrict__ len_out,
       const int* __restrict__ lengths,
       int B, int N, int NB, int Dv, int nchunks)
{
    __shared__ int    soff[1056];       // N+1 exclusive offsets (+ total at [N])
    __shared__ int    stok[T_CHUNK];    // token index per t in chunk (-1 = pad)
    __shared__ float4 sred[256];

    int b     = blockIdx.x;             // fastest-varying: write locality
    int chunk = blockIdx.y;
    int t0    = chunk * T_CHUNK;
    int tid   = threadIdx.x;
    int nbase = b * N;

    // ---- Phase 0: in-block offset scan (warp 0, shuffle) ----
    if (N == 64) {
        if (tid < 32) {
            int l0 = __ldg(&lengths[nbase + 2 * tid]);
            int l1 = __ldg(&lengths[nbase + 2 * tid + 1]);
            int s  = l0 + l1;
            #pragma unroll
            for (int st = 1; st < 32; st <<= 1) {
                int v = __shfl_up_sync(0xffffffffu, s, st);
                if (tid >= st) s += v;
            }
            soff[2 * tid + 1] = s - l1;
            soff[2 * tid + 2] = s;
            if (tid == 0) soff[0] = 0;
        }
    } else {
        if (tid == 0) {
            int acc = 0;
            soff[0] = 0;
            for (int n = 0; n < N; n++) { acc += lengths[nbase + n]; soff[n + 1] = acc; }
        }
    }
    __syncthreads();
    int total = soff[N];
    if (chunk == 0 && tid == 0) {
        len_out[b] = (float)total;
        g_lenf[b]  = (float)total;
    }

    // ---- Phase 1: resolve each t -> token via independent binary search ----
    if (tid < T_CHUNK) {
        int t = t0 + tid;
        int tok = -1;
        float sval = 1.0f;
        if (t < total) {
            int lo = 0, hi = N - 1;                // largest n: soff[n] <= t
            while (lo < hi) {
                int mid = (lo + hi + 1) >> 1;
                if (soff[mid] <= t) lo = mid; else hi = mid - 1;
            }
            int p = t - soff[lo];
            tok  = p * NB + nbase + lo;
            sval = src[p * NB + __ldg(&recover[nbase + lo])];
        }
        stok[tid] = tok;
        src_out[t * B + b] = sval;
    }
    __syncthreads();

    // ---- Phase 2: main stream with explicit 8-deep load batching ----
    int d4 = tid & 63;
    int ts = tid >> 6;

    float4 acc = make_float4(0.f, 0.f, 0.f, 0.f);
    const float4 zero = make_float4(0.f, 0.f, 0.f, 0.f);

    long wbase = (long)(t0 * B + b) * Dv + d4;     // mb_out index for tt=0
    long wstr  = (long)B * Dv;                     // per-t stride

    #pragma unroll
    for (int step = 0; step < T_CHUNK / 32; step++) {
        int base = step * 32 + ts;                 // rows: base, +4, ..., +28
        int tok0 = stok[base];
        int tok1 = stok[base + 4];
        int tok2 = stok[base + 8];
        int tok3 = stok[base + 12];
        int tok4 = stok[base + 16];
        int tok5 = stok[base + 20];
        int tok6 = stok[base + 24];
        int tok7 = stok[base + 28];

        float4 v0 = zero, v1 = zero, v2 = zero, v3 = zero;
        float4 v4 = zero, v5 = zero, v6 = zero, v7 = zero;
        if (tok0 >= 0) v0 = __ldcs(&mb[(long)tok0 * Dv + d4]);
        if (tok1 >= 0) v1 = __ldcs(&mb[(long)tok1 * Dv + d4]);
        if (tok2 >= 0) v2 = __ldcs(&mb[(long)tok2 * Dv + d4]);
        if (tok3 >= 0) v3 = __ldcs(&mb[(long)tok3 * Dv + d4]);
        if (tok4 >= 0) v4 = __ldcs(&mb[(long)tok4 * Dv + d4]);
        if (tok5 >= 0) v5 = __ldcs(&mb[(long)tok5 * Dv + d4]);
        if (tok6 >= 0) v6 = __ldcs(&mb[(long)tok6 * Dv + d4]);
        if (tok7 >= 0) v7 = __ldcs(&mb[(long)tok7 * Dv + d4]);

        __stcs(&mb_out[wbase + (long)(base)      * wstr], v0);
        __stcs(&mb_out[wbase + (long)(base + 4)  * wstr], v1);
        __stcs(&mb_out[wbase + (long)(base + 8)  * wstr], v2);
        __stcs(&mb_out[wbase + (long)(base + 12) * wstr], v3);
        __stcs(&mb_out[wbase + (long)(base + 16) * wstr], v4);
        __stcs(&mb_out[wbase + (long)(base + 20) * wstr], v5);
        __stcs(&mb_out[wbase + (long)(base + 24) * wstr], v6);
        __stcs(&mb_out[wbase + (long)(base + 28) * wstr], v7);

        acc.x += ((v0.x + v1.x) + (v2.x + v3.x)) + ((v4.x + v5.x) + (v6.x + v7.x));
        acc.y += ((v0.y + v1.y) + (v2.y + v3.y)) + ((v4.y + v5.y) + (v6.y + v7.y));
        acc.z += ((v0.z + v1.z) + (v2.z + v3.z)) + ((v4.z + v5.z) + (v6.z + v7.z));
        acc.w += ((v0.w + v1.w) + (v2.w + v3.w)) + ((v4.w + v5.w) + (v6.w + v7.w));
    }

    // ---- Phase 3: deterministic block reduction -> chunk partial ----
    sred[tid] = acc;
    __syncthreads();
    if (ts == 0) {
        float4 a0 = sred[d4];
        float4 a1 = sred[64  + d4];
        float4 a2 = sred[128 + d4];
        float4 a3 = sred[192 + d4];
        float4 tot;
        tot.x = (a0.x + a1.x) + (a2.x + a3.x);
        tot.y = (a0.y + a1.y) + (a2.y + a3.y);
        tot.z = (a0.z + a1.z) + (a2.z + a3.z);
        tot.w = (a0.w + a1.w) + (a2.w + a3.w);
        float4* pp = (float4*)g_partial;
        pp[(long)(b * nchunks + chunk) * Dv + d4] = tot;
    }

    // PDL: let the dependent k_final start its launch/prologue early.
    asm volatile("griddepcontrol.launch_dependents;" ::: "memory");
}

// ---------------------------------------------------------------------------
// Final: grid = (B, D/64), block = 256, PDL-serialized on k_main.
__global__ void __launch_bounds__(256)
k_final(float* __restrict__ hid_out, int D, int nch)
{
    asm volatile("griddepcontrol.wait;" ::: "memory");

    __shared__ float sred[256];
    int b   = blockIdx.x;
    int d0  = blockIdx.y * 64;
    int tid = threadIdx.x;
    int dl  = tid & 63;
    int cg  = tid >> 6;                 // 0..3
    int cpg = nch / 4;                  // 16

    const float* p = g_partial + ((long)b * nch + (long)cg * cpg) * D + d0 + dl;
    float s = 0.f;
    #pragma unroll 16
    for (int c = 0; c < cpg; c++)
        s += p[(long)c * D];

    sred[tid] = s;
    __syncthreads();
    if (cg == 0) {
        float tot = (sred[dl] + sred[64 + dl]) + (sred[128 + dl] + sred[192 + dl]);
        hid_out[b * D + d0 + dl] = tot / g_lenf[b];
    }
}

// ---------------------------------------------------------------------------
extern "C" void kernel_launch(void* const* d_in, const int* in_sizes, int n_in,
                              void* d_out, int out_size)
{
    const float* src     = (const float*)d_in[0];   // [L, NB, 1]
    const float* mb      = (const float*)d_in[1];   // [L, NB, D]
    const int*   lengths = (const int*)  d_in[2];   // [NB]
    const int*   recover = (const int*)  d_in[3];   // [NB]

    int NB = in_sizes[2];
    int L  = in_sizes[0] / NB;
    int D  = in_sizes[1] / in_sizes[0];

    // out_size = NB*L*(1+D) + B*(D+1)  ->  solve for B.
    long rem = (long)out_size - (long)NB * L * (1 + D);
    int B = (int)(rem / (D + 1));
    int N = NB / B;
    int MAX_LEN = N * L;

    float* out      = (float*)d_out;
    float* src_out  = out;                                   // [MAX_LEN, B, 1]
    float* mb_out   = out + (long)MAX_LEN * B;               // [MAX_LEN, B, D]
    float* hid_out  = mb_out + (long)MAX_LEN * B * D;        // [1, B, D]
    float* len_out  = hid_out + (long)B * D;                 // [B]

    int nchunks = MAX_LEN / T_CHUNK;                         // 64
    dim3 grid(B, nchunks);                                   // b fastest-varying
    k_main<<<grid, 256>>>((const float4*)mb, (float4*)mb_out,
                          src, recover, src_out, len_out,
                          lengths, B, N, NB, D / 4, nchunks);

    // k_final with programmatic dependent launch
    cudaLaunchConfig_t cfg = {};
    cfg.gridDim  = dim3(B, D / 64);
    cfg.blockDim = dim3(256);
    cudaLaunchAttribute attr[1];
    attr[0].id = cudaLaunchAttributeProgrammaticStreamSerialization;
    attr[0].val.programmaticStreamSerializationAllowed = 1;
    cfg.attrs    = attr;
    cfg.numAttrs = 1;
    cudaLaunchKernelEx(&cfg, k_final, hid_out, D, nchunks);
}